// round 9
// baseline (speedup 1.0000x reference)
#include <cuda_runtime.h>
#include <cstdint>

// compressor_17454747091102: bitwise majority vote (>=5 of 8) over packed sign bits.
// out bit set iff >=5 of 8 voters have the bit set (vote sum < 0).
// Bit-sliced carry-save adder -> threshold c8 | (c4 & (c2 | c1)).
// Output buffer dtype is float32 (round-1 evidence): store float32((int32)word).
//
// R4: 1 tile/thread, 1024 blocks -> 9.7us, DRAM 42%, 2-wave tail.
// R8: 2 tiles/thread, 512 blocks -> 6.7us, DRAM 47%, regs=40 => ptxas did NOT
//     hoist the 2nd tile's loads; per-warp MLP stayed at 8, memory half-idle.
// R9: 4 tiles/thread, explicit 2-stage register double buffer (a/b), 16 loads
//     in flight per warp. __launch_bounds__(256,2) grants ~128 regs so the
//     pipeline fits without spills. 256 blocks = single wave.

__device__ __forceinline__ void full_add(uint32_t a, uint32_t b, uint32_t c,
                                         uint32_t& s, uint32_t& cy) {
    uint32_t ab = a ^ b;
    s  = ab ^ c;
    cy = (a & b) | (c & ab);
}

__device__ __forceinline__ uint32_t maj5of8(const uint32_t w[8]) {
    uint32_t s_a, c_a, s_b, c_b, s_c, c_c;
    full_add(w[0], w[1], w[2], s_a, c_a);
    full_add(w[3], w[4], w[5], s_b, c_b);
    full_add(w[6], w[7], s_a, s_c, c_c);
    uint32_t s_d = s_b ^ s_c;          // c1
    uint32_t c_d = s_b & s_c;
    uint32_t s_e, c_e;
    full_add(c_a, c_b, c_c, s_e, c_e);
    uint32_t s_f = s_e ^ c_d;          // c2
    uint32_t c_f = s_e & c_d;
    uint32_t s_g = c_e ^ c_f;          // c4
    uint32_t c_g = c_e & c_f;          // c8
    return c_g | (s_g & (s_f | s_d)); // count >= 5
}

__device__ __forceinline__ float4 maj_tile(const uint4 v[8]) {
    uint32_t wx[8], wy[8], wz[8], ww[8];
#pragma unroll
    for (int t = 0; t < 8; t++) {
        wx[t] = v[t].x; wy[t] = v[t].y; wz[t] = v[t].z; ww[t] = v[t].w;
    }
    float4 r;
    r.x = (float)(int)maj5of8(wx);
    r.y = (float)(int)maj5of8(wy);
    r.z = (float)(int)maj5of8(wz);
    r.w = (float)(int)maj5of8(ww);
    return r;
}

__device__ __forceinline__ void load_tile(uint4 v[8], const uint4* __restrict__ src,
                                          int m4, int idx) {
#pragma unroll
    for (int t = 0; t < 8; t++)
        v[t] = src[(size_t)t * m4 + idx];
}

__global__ void __launch_bounds__(256, 2)
compressor_17454747091102_kernel(const uint4* __restrict__ src,
                                 float4* __restrict__ out,
                                 int m4, int q) {
    int i = blockIdx.x * blockDim.x + threadIdx.x;
    if (i >= q) return;

    uint4 a[8], b[8];

    // Stage 0/1: fill both buffers -> 16 LDG.128 in flight.
    load_tile(a, src, m4, i);
    load_tile(b, src, m4, i + q);

    // Consume a (tile 0), immediately refill with tile 2 while b is in flight.
    out[i] = maj_tile(a);
    load_tile(a, src, m4, i + 2 * q);

    // Consume b (tile 1), refill with tile 3 while a is in flight.
    out[i + q] = maj_tile(b);
    load_tile(b, src, m4, i + 3 * q);

    // Drain.
    out[i + 2 * q] = maj_tile(a);
    out[i + 3 * q] = maj_tile(b);
}

extern "C" void kernel_launch(void* const* d_in, const int* in_sizes, int n_in,
                              void* d_out, int out_size) {
    // d_in[0] = para_temp (float, unused), d_in[1] = src_tensor_list (int32, 8*M)
    const uint4* src = (const uint4*)d_in[1];
    float4* out = (float4*)d_out;
    int M  = in_sizes[1] / 8;    // packed words per voter (2^20)
    int m4 = M / 4;              // uint4 tiles per voter (262144)
    int q  = m4 / 4;             // tiles per pass (65536)
    int threads = 256;
    int blocks = (q + threads - 1) / threads;   // 256
    compressor_17454747091102_kernel<<<blocks, threads>>>(src, out, m4, q);
}